// round 14
// baseline (speedup 1.0000x reference)
#include <cuda_runtime.h>
#include <cuda_fp16.h>
#include <math.h>

#define N_NODES   100000
#define N_EDGES   3200000
#define FAN_IN    512
#define FAN_MID   256
#define FAN_OUT   64
#define ELL_PAD   128     // max supported in-degree (Poisson(32): P(>=128) ~ 1e-40)

// ---------------------------------------------------------------------------
// Scratch (device globals; allocation forbidden)
// ---------------------------------------------------------------------------
__device__ __half g_sup1[(size_t)N_NODES * FAN_MID];   // x @ W1      (fp16)
__device__ __half g_h   [(size_t)N_NODES * FAN_MID];   // lrelu(...)  (fp16)
__device__ __half g_sup2[(size_t)N_NODES * FAN_OUT];   // h @ W2      (fp16)
__device__ __half g_w1t [FAN_MID * FAN_IN];            // W1^T fp16 [n][k]
__device__ __half g_w2t [FAN_OUT * FAN_MID];           // W2^T fp16 [n][k]

__device__ int   g_cnt[N_NODES];
__device__ int2  g_csr[(size_t)N_NODES * ELL_PAD];     // ELL: {src, w1h|w2h<<16}

// ---------------------------------------------------------------------------
// Packed f32x2 helpers (sm_100-family PTX; base target OK, unlike tcgen05)
// ---------------------------------------------------------------------------
__device__ __forceinline__ unsigned long long pack_f32x2(float lo, float hi) {
    unsigned long long u;
    asm("mov.b64 %0, {%1, %2};" : "=l"(u) : "f"(lo), "f"(hi));
    return u;
}
__device__ __forceinline__ void unpack_f32x2(unsigned long long u, float& lo, float& hi) {
    asm("mov.b64 {%0, %1}, %2;" : "=f"(lo), "=f"(hi) : "l"(u));
}
__device__ __forceinline__ void fma_f32x2(unsigned long long& d, unsigned long long a,
                                          unsigned long long b) {
    asm("fma.rn.f32x2 %0, %1, %2, %0;" : "+l"(d) : "l"(a), "l"(b));
}

// ---------------------------------------------------------------------------
// Prep: convert W1->w1t, W2->w2t (transposed fp16), zero cnt. One kernel.
// ---------------------------------------------------------------------------
#define W1_ELEMS (FAN_IN * FAN_MID)     // 131072
#define W2_ELEMS (FAN_MID * FAN_OUT)    // 16384
#define PREP_TOTAL (W1_ELEMS + W2_ELEMS + N_NODES)

__global__ void prep_kernel(const float* __restrict__ W1, const float* __restrict__ W2,
                            __half* __restrict__ w1t, __half* __restrict__ w2t,
                            int* __restrict__ cnt) {
    int st = gridDim.x * blockDim.x;
    for (int idx = blockIdx.x * blockDim.x + threadIdx.x; idx < PREP_TOTAL; idx += st) {
        if (idx < W1_ELEMS) {
            int k = idx / FAN_MID, n = idx % FAN_MID;
            w1t[n * FAN_IN + k] = __float2half(W1[idx]);
        } else if (idx < W1_ELEMS + W2_ELEMS) {
            int j = idx - W1_ELEMS;
            int k = j / FAN_OUT, n = j % FAN_OUT;
            w2t[n * FAN_MID + k] = __float2half(W2[j]);
        } else {
            cnt[idx - W1_ELEMS - W2_ELEMS] = 0;
        }
    }
}

// ---------------------------------------------------------------------------
// ELL fill: one pass, 8 edges/iteration, 8 independent slot-atomics in flight.
// ---------------------------------------------------------------------------
__device__ __forceinline__ int pack_w12(float w1, float w2) {
    __half2 h = __floats2half2_rn(w1, w2);   // low = w1, high = w2
    return *(int*)&h;
}

__global__ void fill_kernel(const int* __restrict__ src, const int* __restrict__ dst,
                            const float* __restrict__ w1, const float* __restrict__ w2,
                            int* __restrict__ cnt, int2* __restrict__ csr, int E) {
    int st = gridDim.x * blockDim.x;
    int gid = blockIdx.x * blockDim.x + threadIdx.x;
    int nq = E >> 3;
    for (int q = gid; q < nq; q += st) {
        int4 d0 = ((const int4*)dst)[q * 2];
        int4 d1 = ((const int4*)dst)[q * 2 + 1];
        int4 s0 = ((const int4*)src)[q * 2];
        int4 s1 = ((const int4*)src)[q * 2 + 1];
        float4 a0 = ((const float4*)w1)[q * 2];
        float4 a1 = ((const float4*)w1)[q * 2 + 1];
        float4 b0 = ((const float4*)w2)[q * 2];
        float4 b1 = ((const float4*)w2)[q * 2 + 1];
        int p0 = atomicAdd(&cnt[d0.x], 1);
        int p1 = atomicAdd(&cnt[d0.y], 1);
        int p2 = atomicAdd(&cnt[d0.z], 1);
        int p3 = atomicAdd(&cnt[d0.w], 1);
        int p4 = atomicAdd(&cnt[d1.x], 1);
        int p5 = atomicAdd(&cnt[d1.y], 1);
        int p6 = atomicAdd(&cnt[d1.z], 1);
        int p7 = atomicAdd(&cnt[d1.w], 1);
        if (p0 < ELL_PAD) csr[(size_t)d0.x * ELL_PAD + p0] = make_int2(s0.x, pack_w12(a0.x, b0.x));
        if (p1 < ELL_PAD) csr[(size_t)d0.y * ELL_PAD + p1] = make_int2(s0.y, pack_w12(a0.y, b0.y));
        if (p2 < ELL_PAD) csr[(size_t)d0.z * ELL_PAD + p2] = make_int2(s0.z, pack_w12(a0.z, b0.z));
        if (p3 < ELL_PAD) csr[(size_t)d0.w * ELL_PAD + p3] = make_int2(s0.w, pack_w12(a0.w, b0.w));
        if (p4 < ELL_PAD) csr[(size_t)d1.x * ELL_PAD + p4] = make_int2(s1.x, pack_w12(a1.x, b1.x));
        if (p5 < ELL_PAD) csr[(size_t)d1.y * ELL_PAD + p5] = make_int2(s1.y, pack_w12(a1.y, b1.y));
        if (p6 < ELL_PAD) csr[(size_t)d1.z * ELL_PAD + p6] = make_int2(s1.z, pack_w12(a1.z, b1.z));
        if (p7 < ELL_PAD) csr[(size_t)d1.w * ELL_PAD + p7] = make_int2(s1.w, pack_w12(a1.w, b1.w));
    }
    for (int i = (nq << 3) + gid; i < E; i += st) {
        int d = dst[i];
        int pos = atomicAdd(&cnt[d], 1);
        if (pos < ELL_PAD) csr[(size_t)d * ELL_PAD + pos] = make_int2(src[i], pack_w12(w1[i], w2[i]));
    }
}

// ---------------------------------------------------------------------------
// mma / cp.async / ldmatrix helpers
// ---------------------------------------------------------------------------
__device__ __forceinline__ unsigned pack_h2(float lo, float hi) {
    __half2 h = __floats2half2_rn(lo, hi);
    return *(unsigned*)&h;
}

__device__ __forceinline__ void mma_f16(float& c0, float& c1, float& c2, float& c3,
                                        unsigned a0, unsigned a1, unsigned a2, unsigned a3,
                                        unsigned b0, unsigned b1) {
    asm volatile(
        "mma.sync.aligned.m16n8k16.row.col.f32.f16.f16.f32 "
        "{%0,%1,%2,%3}, {%4,%5,%6,%7}, {%8,%9}, {%0,%1,%2,%3};"
        : "+f"(c0), "+f"(c1), "+f"(c2), "+f"(c3)
        : "r"(a0), "r"(a1), "r"(a2), "r"(a3), "r"(b0), "r"(b1));
}

__device__ __forceinline__ void ldsm_x4(unsigned& r0, unsigned& r1, unsigned& r2, unsigned& r3,
                                        unsigned addr) {
    asm volatile("ldmatrix.sync.aligned.m8n8.x4.shared.b16 {%0,%1,%2,%3}, [%4];"
                 : "=r"(r0), "=r"(r1), "=r"(r2), "=r"(r3) : "r"(addr));
}

__device__ __forceinline__ unsigned smem_u32(const void* p) {
    return (unsigned)__cvta_generic_to_shared(p);
}

__device__ __forceinline__ void cp_async16(unsigned dst, const void* gsrc, int src_bytes) {
    asm volatile("cp.async.cg.shared.global [%0], [%1], 16, %2;"
                 :: "r"(dst), "l"(gsrc), "r"(src_bytes));
}
__device__ __forceinline__ void cp_commit() { asm volatile("cp.async.commit_group;"); }
template <int NW>
__device__ __forceinline__ void cp_wait() { asm volatile("cp.async.wait_group %0;" :: "n"(NW)); }

// ---------------------------------------------------------------------------
// GEMM1: A fp32 (x), B = W1^T fp16 [n][k]. BM=128, BN=256, BK=32.
// ---------------------------------------------------------------------------
template <int BN, int KDIM>
__global__ __launch_bounds__(256) void gemm1_kernel(
    const float* __restrict__ A, const __half* __restrict__ Bt,
    __half* __restrict__ C, int M, int N) {
    constexpr int NT = BN / 16;          // 16
    constexpr int NP = NT / 2;           // 8 LDSM groups
    constexpr int A_STAGE = 128 * 36;    // floats
    constexpr int B_STAGE = BN * 40;     // halves
    extern __shared__ char smraw[];
    float*  Asm = (float*)smraw;
    __half* Bsm = (__half*)(smraw + 2 * A_STAGE * 4);

    const int tid = threadIdx.x;
    const int lane = tid & 31;
    const int wid = tid >> 5;
    const int warp_m = wid & 3;
    const int warp_n = wid >> 2;
    const int bm = blockIdx.y * 128;
    const int bn = blockIdx.x * BN;
    const int g = lane >> 2;
    const int tg = lane & 3;
    const int lr = lane & 7;
    const int sel = lane >> 3;
    const int brow0 = warp_n * (BN / 2) + ((sel >> 1) & 1) * 8 + lr;
    const int bkoff = (sel & 1) * 8;

    float acc[2][NT][4];
    #pragma unroll
    for (int i = 0; i < 2; i++)
        #pragma unroll
        for (int j = 0; j < NT; j++)
            #pragma unroll
            for (int c = 0; c < 4; c++) acc[i][j][c] = 0.0f;

    constexpr int ktiles = KDIM / 32;

    auto load_stage = [&](int s, int k0) {
        float* As = Asm + s * A_STAGE;
        __half* Bs = Bsm + s * B_STAGE;
        #pragma unroll
        for (int i = 0; i < 4; i++) {
            int f4 = tid + i * 256;
            int row = f4 >> 3;
            int kq = (f4 & 7) * 4;
            int grow = bm + row;
            int ok = (grow < M);
            const float* gp = A + (size_t)(ok ? grow : 0) * KDIM + k0 + kq;
            cp_async16(smem_u32(&As[row * 36 + kq]), gp, ok ? 16 : 0);
        }
        constexpr int BC = BN * 4 / 256;
        #pragma unroll
        for (int i = 0; i < BC; i++) {
            int c = tid + i * 256;
            int nrow = c >> 2;
            int hq = (c & 3) * 8;
            const __half* gp = Bt + (size_t)(bn + nrow) * KDIM + k0 + hq;
            cp_async16(smem_u32(&Bs[nrow * 40 + hq]), gp, 16);
        }
        cp_commit();
    };

    load_stage(0, 0);

    for (int t = 0; t < ktiles; t++) {
        if (t + 1 < ktiles) load_stage((t + 1) & 1, (t + 1) * 32);
        else cp_commit();
        cp_wait<1>();
        __syncthreads();

        const float* As = Asm + (t & 1) * A_STAGE;
        const __half* Bs = Bsm + (t & 1) * B_STAGE;
        const unsigned bbase = smem_u32(Bs) + (unsigned)(brow0 * 40 + bkoff) * 2;

        #pragma unroll
        for (int kk = 0; kk < 32; kk += 16) {
            unsigned a[2][4];
            #pragma unroll
            for (int mt = 0; mt < 2; mt++) {
                int rb = warp_m * 32 + mt * 16 + g;
                float2 p0 = *(const float2*)&As[rb * 36 + kk + 2 * tg];
                float2 p1 = *(const float2*)&As[(rb + 8) * 36 + kk + 2 * tg];
                float2 p2 = *(const float2*)&As[rb * 36 + kk + 8 + 2 * tg];
                float2 p3 = *(const float2*)&As[(rb + 8) * 36 + kk + 8 + 2 * tg];
                a[mt][0] = pack_h2(p0.x, p0.y);
                a[mt][1] = pack_h2(p1.x, p1.y);
                a[mt][2] = pack_h2(p2.x, p2.y);
                a[mt][3] = pack_h2(p3.x, p3.y);
            }
            #pragma unroll
            for (int np = 0; np < NP; np++) {
                unsigned b0, b1, b2, b3;
                ldsm_x4(b0, b1, b2, b3, bbase + np * 16 * 40 * 2 + kk * 2);
                #pragma unroll
                for (int mt = 0; mt < 2; mt++) {
                    mma_f16(acc[mt][2 * np][0], acc[mt][2 * np][1], acc[mt][2 * np][2], acc[mt][2 * np][3],
                            a[mt][0], a[mt][1], a[mt][2], a[mt][3], b0, b1);
                    mma_f16(acc[mt][2 * np + 1][0], acc[mt][2 * np + 1][1], acc[mt][2 * np + 1][2], acc[mt][2 * np + 1][3],
                            a[mt][0], a[mt][1], a[mt][2], a[mt][3], b2, b3);
                }
            }
        }
        __syncthreads();
    }

    #pragma unroll
    for (int mt = 0; mt < 2; mt++) {
        #pragma unroll
        for (int nt = 0; nt < NT; nt++) {
            int col = bn + warp_n * (BN / 2) + nt * 8 + tg * 2;
            int r0 = bm + warp_m * 32 + mt * 16 + g;
            int r1 = r0 + 8;
            if (r0 < M)
                *(__half2*)&C[(size_t)r0 * N + col] = __floats2half2_rn(acc[mt][nt][0], acc[mt][nt][1]);
            if (r1 < M)
                *(__half2*)&C[(size_t)r1 * N + col] = __floats2half2_rn(acc[mt][nt][2], acc[mt][nt][3]);
        }
    }
}

// ---------------------------------------------------------------------------
// GEMM2: A fp16 (h), B = W2^T fp16 [n][k]. BM=128, BN=64, BK=32.
// ---------------------------------------------------------------------------
__global__ __launch_bounds__(256) void gemm2_kernel(
    const __half* __restrict__ A, const __half* __restrict__ Bt,
    __half* __restrict__ C, int M, int N, int K) {
    constexpr int BN = 64, NT = BN / 16, NP = NT / 2;  // 4, 2
    constexpr int A_STAGE = 128 * 56;    // halves
    constexpr int B_STAGE = BN * 40;     // halves
    extern __shared__ char smraw[];
    __half* Asm = (__half*)smraw;
    __half* Bsm = (__half*)(smraw + 2 * A_STAGE * 2);

    const int tid = threadIdx.x;
    const int lane = tid & 31;
    const int wid = tid >> 5;
    const int warp_m = wid & 3;
    const int warp_n = wid >> 2;
    const int bm = blockIdx.y * 128;
    const int bn = blockIdx.x * BN;
    const int g = lane >> 2;
    const int tg = lane & 3;
    const int lr = lane & 7;
    const int sel = lane >> 3;
    const int arow0 = warp_m * 32 + (sel & 1) * 8 + lr;
    const int akoff = ((sel >> 1) & 1) * 8;
    const int brow0 = warp_n * (BN / 2) + ((sel >> 1) & 1) * 8 + lr;
    const int bkoff = (sel & 1) * 8;

    float acc[2][NT][4];
    #pragma unroll
    for (int i = 0; i < 2; i++)
        #pragma unroll
        for (int j = 0; j < NT; j++)
            #pragma unroll
            for (int c = 0; c < 4; c++) acc[i][j][c] = 0.0f;

    const int ktiles = K / 32;

    auto load_stage = [&](int s, int k0) {
        __half* As = Asm + s * A_STAGE;
        __half* Bs = Bsm + s * B_STAGE;
        #pragma unroll
        for (int i = 0; i < 2; i++) {
            int c = tid + i * 256;
            int row = c >> 2;
            int hq = (c & 3) * 8;
            int grow = bm + row;
            int ok = (grow < M);
            const __half* gp = A + (size_t)(ok ? grow : 0) * K + k0 + hq;
            cp_async16(smem_u32(&As[row * 56 + hq]), gp, ok ? 16 : 0);
        }
        {
            int c = tid;
            int nrow = c >> 2;
            int hq = (c & 3) * 8;
            const __half* gp = Bt + (size_t)(bn + nrow) * K + k0 + hq;
            cp_async16(smem_u32(&Bs[nrow * 40 + hq]), gp, 16);
        }
        cp_commit();
    };

    load_stage(0, 0);

    for (int t = 0; t < ktiles; t++) {
        if (t + 1 < ktiles) load_stage((t + 1) & 1, (t + 1) * 32);
        else cp_commit();
        cp_wait<1>();
        __syncthreads();

        const __half* As = Asm + (t & 1) * A_STAGE;
        const __half* Bs = Bsm + (t & 1) * B_STAGE;
        const unsigned abase = smem_u32(As) + (unsigned)(arow0 * 56 + akoff) * 2;
        const unsigned bbase = smem_u32(Bs) + (unsigned)(brow0 * 40 + bkoff) * 2;

        #pragma unroll
        for (int kk = 0; kk < 32; kk += 16) {
            unsigned a[2][4];
            #pragma unroll
            for (int mt = 0; mt < 2; mt++)
                ldsm_x4(a[mt][0], a[mt][1], a[mt][2], a[mt][3],
                        abase + mt * 16 * 56 * 2 + kk * 2);
            #pragma unroll
            for (int np = 0; np < NP; np++) {
                unsigned b0, b1, b2, b3;
                ldsm_x4(b0, b1, b2, b3, bbase + np * 16 * 40 * 2 + kk * 2);
                #pragma unroll
                for (int mt = 0; mt < 2; mt++) {
                    mma_f16(acc[mt][2 * np][0], acc[mt][2 * np][1], acc[mt][2 * np][2], acc[mt][2 * np][3],
                            a[mt][0], a[mt][1], a[mt][2], a[mt][3], b0, b1);
                    mma_f16(acc[mt][2 * np + 1][0], acc[mt][2 * np + 1][1], acc[mt][2 * np + 1][2], acc[mt][2 * np + 1][3],
                            a[mt][0], a[mt][1], a[mt][2], a[mt][3], b2, b3);
                }
            }
        }
        __syncthreads();
    }

    #pragma unroll
    for (int mt = 0; mt < 2; mt++) {
        #pragma unroll
        for (int nt = 0; nt < NT; nt++) {
            int col = bn + warp_n * (BN / 2) + nt * 8 + tg * 2;
            int r0 = bm + warp_m * 32 + mt * 16 + g;
            int r1 = r0 + 8;
            if (r0 < M)
                *(__half2*)&C[(size_t)r0 * N + col] = __floats2half2_rn(acc[mt][nt][0], acc[mt][nt][1]);
            if (r1 < M)
                *(__half2*)&C[(size_t)r1 * N + col] = __floats2half2_rn(acc[mt][nt][2], acc[mt][nt][3]);
        }
    }
}

// ---------------------------------------------------------------------------
// Gather layer 1 (F=256): warp/node, 8 feats/lane, 4-edge unroll, f32x2 FMA.
// ---------------------------------------------------------------------------
__device__ __forceinline__ void g1_accum(unsigned long long& a0, unsigned long long& a1,
                                         unsigned long long& a2, unsigned long long& a3,
                                         uint4 r, unsigned long long ww) {
    float2 f0 = __half22float2(*(__half2*)&r.x);
    float2 f1 = __half22float2(*(__half2*)&r.y);
    float2 f2 = __half22float2(*(__half2*)&r.z);
    float2 f3 = __half22float2(*(__half2*)&r.w);
    fma_f32x2(a0, pack_f32x2(f0.x, f0.y), ww);
    fma_f32x2(a1, pack_f32x2(f1.x, f1.y), ww);
    fma_f32x2(a2, pack_f32x2(f2.x, f2.y), ww);
    fma_f32x2(a3, pack_f32x2(f3.x, f3.y), ww);
}

__global__ void gather1_kernel(const int* __restrict__ cnt, const int2* __restrict__ csr,
                               const __half* __restrict__ sup, const float* __restrict__ b,
                               __half* __restrict__ h, int n) {
    int node = blockIdx.x * 8 + (threadIdx.x >> 5);
    if (node >= n) return;
    int lane = threadIdx.x & 31;
    int p0 = node * ELL_PAD;
    int deg = cnt[node];
    if (deg > ELL_PAD) deg = ELL_PAD;
    int p1 = p0 + deg;
    const __half* supl = sup + lane * 8;   // hoisted lane offset (32-bit addressing below)

    unsigned long long a0 = 0, a1 = 0, a2 = 0, a3 = 0;
    int p = p0;
    for (; p + 4 <= p1; p += 4) {
        int2 e0 = __ldg(&csr[p]);
        int2 e1 = __ldg(&csr[p + 1]);
        int2 e2 = __ldg(&csr[p + 2]);
        int2 e3 = __ldg(&csr[p + 3]);
        uint4 r0 = *(const uint4*)(supl + ((unsigned)e0.x << 8));
        uint4 r1 = *(const uint4*)(supl + ((unsigned)e1.x << 8));
        uint4 r2 = *(const uint4*)(supl + ((unsigned)e2.x << 8));
        uint4 r3 = *(const uint4*)(supl + ((unsigned)e3.x << 8));
        float w0 = __low2float(*(__half2*)&e0.y);
        float w1 = __low2float(*(__half2*)&e1.y);
        float w2 = __low2float(*(__half2*)&e2.y);
        float w3 = __low2float(*(__half2*)&e3.y);
        g1_accum(a0, a1, a2, a3, r0, pack_f32x2(w0, w0));
        g1_accum(a0, a1, a2, a3, r1, pack_f32x2(w1, w1));
        g1_accum(a0, a1, a2, a3, r2, pack_f32x2(w2, w2));
        g1_accum(a0, a1, a2, a3, r3, pack_f32x2(w3, w3));
    }
    for (; p < p1; p++) {
        int2 e0 = __ldg(&csr[p]);
        float w0 = __low2float(*(__half2*)&e0.y);
        uint4 r0 = *(const uint4*)(supl + ((unsigned)e0.x << 8));
        g1_accum(a0, a1, a2, a3, r0, pack_f32x2(w0, w0));
    }

    float acc[8];
    unpack_f32x2(a0, acc[0], acc[1]);
    unpack_f32x2(a1, acc[2], acc[3]);
    unpack_f32x2(a2, acc[4], acc[5]);
    unpack_f32x2(a3, acc[6], acc[7]);
    float4 b0 = *(const float4*)&b[lane * 8];
    float4 b1 = *(const float4*)&b[lane * 8 + 4];
    acc[0] += b0.x; acc[1] += b0.y; acc[2] += b0.z; acc[3] += b0.w;
    acc[4] += b1.x; acc[5] += b1.y; acc[6] += b1.z; acc[7] += b1.w;
    #pragma unroll
    for (int j = 0; j < 8; j++) acc[j] = (acc[j] > 0.f) ? acc[j] : 0.01f * acc[j];
    uint4 outw;
    *(__half2*)&outw.x = __floats2half2_rn(acc[0], acc[1]);
    *(__half2*)&outw.y = __floats2half2_rn(acc[2], acc[3]);
    *(__half2*)&outw.z = __floats2half2_rn(acc[4], acc[5]);
    *(__half2*)&outw.w = __floats2half2_rn(acc[6], acc[7]);
    *(uint4*)&h[(size_t)node * FAN_MID + lane * 8] = outw;
}

// ---------------------------------------------------------------------------
// Gather layer 2 (F=64) fused with bias + log_softmax. f32x2 FMA.
// ---------------------------------------------------------------------------
__global__ void gather2_lsm_kernel(const int* __restrict__ cnt, const int2* __restrict__ csr,
                                   const __half* __restrict__ sup, const float* __restrict__ b,
                                   float* __restrict__ out, int n) {
    int node = blockIdx.x * 8 + (threadIdx.x >> 5);
    if (node >= n) return;
    int lane = threadIdx.x & 31;
    int p0 = node * ELL_PAD;
    int deg = cnt[node];
    if (deg > ELL_PAD) deg = ELL_PAD;
    int p1 = p0 + deg;
    const __half* supl = sup + lane * 2;

    unsigned long long acc2 = 0;
    int p = p0;
    for (; p + 4 <= p1; p += 4) {
        int2 e0 = __ldg(&csr[p]);
        int2 e1 = __ldg(&csr[p + 1]);
        int2 e2 = __ldg(&csr[p + 2]);
        int2 e3 = __ldg(&csr[p + 3]);
        float2 f0 = __half22float2(*(const __half2*)(supl + ((unsigned)e0.x << 6)));
        float2 f1 = __half22float2(*(const __half2*)(supl + ((unsigned)e1.x << 6)));
        float2 f2 = __half22float2(*(const __half2*)(supl + ((unsigned)e2.x << 6)));
        float2 f3 = __half22float2(*(const __half2*)(supl + ((unsigned)e3.x << 6)));
        float w0 = __high2float(*(__half2*)&e0.y);
        float w1 = __high2float(*(__half2*)&e1.y);
        float w2 = __high2float(*(__half2*)&e2.y);
        float w3 = __high2float(*(__half2*)&e3.y);
        fma_f32x2(acc2, pack_f32x2(f0.x, f0.y), pack_f32x2(w0, w0));
        fma_f32x2(acc2, pack_f32x2(f1.x, f1.y), pack_f32x2(w1, w1));
        fma_f32x2(acc2, pack_f32x2(f2.x, f2.y), pack_f32x2(w2, w2));
        fma_f32x2(acc2, pack_f32x2(f3.x, f3.y), pack_f32x2(w3, w3));
    }
    for (; p < p1; p++) {
        int2 e0 = __ldg(&csr[p]);
        float w0 = __high2float(*(__half2*)&e0.y);
        float2 f0 = __half22float2(*(const __half2*)(supl + ((unsigned)e0.x << 6)));
        fma_f32x2(acc2, pack_f32x2(f0.x, f0.y), pack_f32x2(w0, w0));
    }
    float a0, a1;
    unpack_f32x2(acc2, a0, a1);
    a0 += b[lane * 2];
    a1 += b[lane * 2 + 1];
    float m = fmaxf(a0, a1);
    #pragma unroll
    for (int o = 16; o; o >>= 1) m = fmaxf(m, __shfl_xor_sync(0xFFFFFFFFu, m, o));
    float s2 = expf(a0 - m) + expf(a1 - m);
    #pragma unroll
    for (int o = 16; o; o >>= 1) s2 += __shfl_xor_sync(0xFFFFFFFFu, s2, o);
    float lse = m + logf(s2);
    out[(size_t)node * FAN_OUT + lane * 2]     = a0 - lse;
    out[(size_t)node * FAN_OUT + lane * 2 + 1] = a1 - lse;
}

// ---------------------------------------------------------------------------
// Launch (single stream, serial)
// ---------------------------------------------------------------------------
extern "C" void kernel_launch(void* const* d_in, const int* in_sizes, int n_in,
                              void* d_out, int out_size) {
    const float* x        = (const float*)d_in[0];
    const int*   edge_src = (const int*)  d_in[1];
    const int*   edge_dst = (const int*)  d_in[2];
    const float* edge_w1  = (const float*)d_in[3];
    const float* edge_w2  = (const float*)d_in[4];
    const float* W1       = (const float*)d_in[5];
    const float* b1       = (const float*)d_in[6];
    const float* W2       = (const float*)d_in[7];
    const float* b2       = (const float*)d_in[8];
    float* out = (float*)d_out;

    const int E = in_sizes[1];
    const int N = in_sizes[0] / FAN_IN;

    __half *sup1, *h, *sup2, *w1t, *w2t;
    int *cnt;
    int2 *csr;
    cudaGetSymbolAddress((void**)&sup1, g_sup1);
    cudaGetSymbolAddress((void**)&h, g_h);
    cudaGetSymbolAddress((void**)&sup2, g_sup2);
    cudaGetSymbolAddress((void**)&w1t, g_w1t);
    cudaGetSymbolAddress((void**)&w2t, g_w2t);
    cudaGetSymbolAddress((void**)&cnt, g_cnt);
    cudaGetSymbolAddress((void**)&csr, g_csr);

    constexpr int SMEM_G1 = 2 * 128 * 36 * 4 + 2 * 256 * 40 * 2;   // 77824
    constexpr int SMEM_G2 = 2 * 128 * 56 * 2 + 2 * 64 * 40 * 2;    // 38912
    static bool s_init = false;
    if (!s_init) {
        cudaFuncSetAttribute(gemm1_kernel<256, FAN_IN>,
                             cudaFuncAttributeMaxDynamicSharedMemorySize, SMEM_G1);
        cudaFuncSetAttribute(gemm2_kernel,
                             cudaFuncAttributeMaxDynamicSharedMemorySize, SMEM_G2);
        s_init = true;
    }

    // --- Prep: weight transpose-convert + zero cnt (one kernel) ---
    prep_kernel<<<512, 256>>>(W1, W2, w1t, w2t, cnt);

    // --- ELL build: single pass ---
    fill_kernel<<<1024, 256>>>(edge_src, edge_dst, edge_w1, edge_w2, cnt, csr, E);

    // --- Layer 1: sup1 = x @ W1 ---
    {
        dim3 grid(1, (N + 127) / 128);
        gemm1_kernel<256, FAN_IN><<<grid, 256, SMEM_G1>>>(x, w1t, sup1, N, FAN_MID);
    }
    // h = lrelu(A @ sup1 + b1), fp16
    gather1_kernel<<<(N + 7) / 8, 256>>>(cnt, csr, sup1, b1, h, N);

    // --- Layer 2: sup2 = h @ W2 ---
    {
        dim3 grid(FAN_OUT / 64, (N + 127) / 128);
        gemm2_kernel<<<grid, 256, SMEM_G2>>>(h, w2t, sup2, N, FAN_OUT, FAN_MID);
    }
    // out = log_softmax(A @ sup2 + b2)
    gather2_lsm_kernel<<<(N + 7) / 8, 256>>>(cnt, csr, sup2, b2, out, N);
}

// round 15
// speedup vs baseline: 1.0520x; 1.0520x over previous
#include <cuda_runtime.h>
#include <cuda_fp16.h>
#include <math.h>

#define N_NODES   100000
#define N_EDGES   3200000
#define FAN_IN    512
#define FAN_MID   256
#define FAN_OUT   64
#define ELL_PAD   128     // max supported in-degree (Poisson(32): P(>=128) ~ 1e-40)

// ---------------------------------------------------------------------------
// Scratch (device globals; allocation forbidden)
// ---------------------------------------------------------------------------
__device__ __half g_sup1[(size_t)N_NODES * FAN_MID];   // x @ W1      (fp16)
__device__ __half g_h   [(size_t)N_NODES * FAN_MID];   // lrelu(...)  (fp16)
__device__ __half g_sup2[(size_t)N_NODES * FAN_OUT];   // h @ W2      (fp16)
__device__ __half g_w1t [FAN_MID * FAN_IN];            // W1^T fp16 [n][k]
__device__ __half g_w2t [FAN_OUT * FAN_MID];           // W2^T fp16 [n][k]

__device__ int   g_cnt[N_NODES];
__device__ int2  g_csr[(size_t)N_NODES * ELL_PAD];     // ELL: {src, w1h|w2h<<16}

// ---------------------------------------------------------------------------
// Prep: convert W1->w1t, W2->w2t (transposed fp16), zero cnt. One kernel.
// ---------------------------------------------------------------------------
#define W1_ELEMS (FAN_IN * FAN_MID)     // 131072
#define W2_ELEMS (FAN_MID * FAN_OUT)    // 16384
#define PREP_TOTAL (W1_ELEMS + W2_ELEMS + N_NODES)

__global__ void prep_kernel(const float* __restrict__ W1, const float* __restrict__ W2,
                            __half* __restrict__ w1t, __half* __restrict__ w2t,
                            int* __restrict__ cnt) {
    int st = gridDim.x * blockDim.x;
    for (int idx = blockIdx.x * blockDim.x + threadIdx.x; idx < PREP_TOTAL; idx += st) {
        if (idx < W1_ELEMS) {
            int k = idx / FAN_MID, n = idx % FAN_MID;
            w1t[n * FAN_IN + k] = __float2half(W1[idx]);
        } else if (idx < W1_ELEMS + W2_ELEMS) {
            int j = idx - W1_ELEMS;
            int k = j / FAN_OUT, n = j % FAN_OUT;
            w2t[n * FAN_MID + k] = __float2half(W2[j]);
        } else {
            cnt[idx - W1_ELEMS - W2_ELEMS] = 0;
        }
    }
}

// ---------------------------------------------------------------------------
// ELL fill: one pass, 8 edges/iteration, 8 independent slot-atomics in flight.
// ---------------------------------------------------------------------------
__device__ __forceinline__ int pack_w12(float w1, float w2) {
    __half2 h = __floats2half2_rn(w1, w2);   // low = w1, high = w2
    return *(int*)&h;
}

__global__ void fill_kernel(const int* __restrict__ src, const int* __restrict__ dst,
                            const float* __restrict__ w1, const float* __restrict__ w2,
                            int* __restrict__ cnt, int2* __restrict__ csr, int E) {
    int st = gridDim.x * blockDim.x;
    int gid = blockIdx.x * blockDim.x + threadIdx.x;
    int nq = E >> 3;
    for (int q = gid; q < nq; q += st) {
        int4 d0 = ((const int4*)dst)[q * 2];
        int4 d1 = ((const int4*)dst)[q * 2 + 1];
        int4 s0 = ((const int4*)src)[q * 2];
        int4 s1 = ((const int4*)src)[q * 2 + 1];
        float4 a0 = ((const float4*)w1)[q * 2];
        float4 a1 = ((const float4*)w1)[q * 2 + 1];
        float4 b0 = ((const float4*)w2)[q * 2];
        float4 b1 = ((const float4*)w2)[q * 2 + 1];
        int p0 = atomicAdd(&cnt[d0.x], 1);
        int p1 = atomicAdd(&cnt[d0.y], 1);
        int p2 = atomicAdd(&cnt[d0.z], 1);
        int p3 = atomicAdd(&cnt[d0.w], 1);
        int p4 = atomicAdd(&cnt[d1.x], 1);
        int p5 = atomicAdd(&cnt[d1.y], 1);
        int p6 = atomicAdd(&cnt[d1.z], 1);
        int p7 = atomicAdd(&cnt[d1.w], 1);
        if (p0 < ELL_PAD) csr[(size_t)d0.x * ELL_PAD + p0] = make_int2(s0.x, pack_w12(a0.x, b0.x));
        if (p1 < ELL_PAD) csr[(size_t)d0.y * ELL_PAD + p1] = make_int2(s0.y, pack_w12(a0.y, b0.y));
        if (p2 < ELL_PAD) csr[(size_t)d0.z * ELL_PAD + p2] = make_int2(s0.z, pack_w12(a0.z, b0.z));
        if (p3 < ELL_PAD) csr[(size_t)d0.w * ELL_PAD + p3] = make_int2(s0.w, pack_w12(a0.w, b0.w));
        if (p4 < ELL_PAD) csr[(size_t)d1.x * ELL_PAD + p4] = make_int2(s1.x, pack_w12(a1.x, b1.x));
        if (p5 < ELL_PAD) csr[(size_t)d1.y * ELL_PAD + p5] = make_int2(s1.y, pack_w12(a1.y, b1.y));
        if (p6 < ELL_PAD) csr[(size_t)d1.z * ELL_PAD + p6] = make_int2(s1.z, pack_w12(a1.z, b1.z));
        if (p7 < ELL_PAD) csr[(size_t)d1.w * ELL_PAD + p7] = make_int2(s1.w, pack_w12(a1.w, b1.w));
    }
    for (int i = (nq << 3) + gid; i < E; i += st) {
        int d = dst[i];
        int pos = atomicAdd(&cnt[d], 1);
        if (pos < ELL_PAD) csr[(size_t)d * ELL_PAD + pos] = make_int2(src[i], pack_w12(w1[i], w2[i]));
    }
}

// ---------------------------------------------------------------------------
// mma / cp.async / ldmatrix helpers
// ---------------------------------------------------------------------------
__device__ __forceinline__ unsigned pack_h2(float lo, float hi) {
    __half2 h = __floats2half2_rn(lo, hi);
    return *(unsigned*)&h;
}

__device__ __forceinline__ void mma_f16(float& c0, float& c1, float& c2, float& c3,
                                        unsigned a0, unsigned a1, unsigned a2, unsigned a3,
                                        unsigned b0, unsigned b1) {
    asm volatile(
        "mma.sync.aligned.m16n8k16.row.col.f32.f16.f16.f32 "
        "{%0,%1,%2,%3}, {%4,%5,%6,%7}, {%8,%9}, {%0,%1,%2,%3};"
        : "+f"(c0), "+f"(c1), "+f"(c2), "+f"(c3)
        : "r"(a0), "r"(a1), "r"(a2), "r"(a3), "r"(b0), "r"(b1));
}

__device__ __forceinline__ void ldsm_x4(unsigned& r0, unsigned& r1, unsigned& r2, unsigned& r3,
                                        unsigned addr) {
    asm volatile("ldmatrix.sync.aligned.m8n8.x4.shared.b16 {%0,%1,%2,%3}, [%4];"
                 : "=r"(r0), "=r"(r1), "=r"(r2), "=r"(r3) : "r"(addr));
}

__device__ __forceinline__ unsigned smem_u32(const void* p) {
    return (unsigned)__cvta_generic_to_shared(p);
}

__device__ __forceinline__ void cp_async16(unsigned dst, const void* gsrc, int src_bytes) {
    asm volatile("cp.async.cg.shared.global [%0], [%1], 16, %2;"
                 :: "r"(dst), "l"(gsrc), "r"(src_bytes));
}
__device__ __forceinline__ void cp_commit() { asm volatile("cp.async.commit_group;"); }
template <int NW>
__device__ __forceinline__ void cp_wait() { asm volatile("cp.async.wait_group %0;" :: "n"(NW)); }

// ---------------------------------------------------------------------------
// GEMM1: A fp32 (x), B = W1^T fp16 [n][k]. BM=128, BN=256, BK=32.
// ---------------------------------------------------------------------------
template <int BN, int KDIM>
__global__ __launch_bounds__(256) void gemm1_kernel(
    const float* __restrict__ A, const __half* __restrict__ Bt,
    __half* __restrict__ C, int M, int N) {
    constexpr int NT = BN / 16;          // 16
    constexpr int NP = NT / 2;           // 8 LDSM groups
    constexpr int A_STAGE = 128 * 36;    // floats
    constexpr int B_STAGE = BN * 40;     // halves
    extern __shared__ char smraw[];
    float*  Asm = (float*)smraw;
    __half* Bsm = (__half*)(smraw + 2 * A_STAGE * 4);

    const int tid = threadIdx.x;
    const int lane = tid & 31;
    const int wid = tid >> 5;
    const int warp_m = wid & 3;
    const int warp_n = wid >> 2;
    const int bm = blockIdx.y * 128;
    const int bn = blockIdx.x * BN;
    const int g = lane >> 2;
    const int tg = lane & 3;
    const int lr = lane & 7;
    const int sel = lane >> 3;
    const int brow0 = warp_n * (BN / 2) + ((sel >> 1) & 1) * 8 + lr;
    const int bkoff = (sel & 1) * 8;

    float acc[2][NT][4];
    #pragma unroll
    for (int i = 0; i < 2; i++)
        #pragma unroll
        for (int j = 0; j < NT; j++)
            #pragma unroll
            for (int c = 0; c < 4; c++) acc[i][j][c] = 0.0f;

    constexpr int ktiles = KDIM / 32;

    auto load_stage = [&](int s, int k0) {
        float* As = Asm + s * A_STAGE;
        __half* Bs = Bsm + s * B_STAGE;
        #pragma unroll
        for (int i = 0; i < 4; i++) {
            int f4 = tid + i * 256;
            int row = f4 >> 3;
            int kq = (f4 & 7) * 4;
            int grow = bm + row;
            int ok = (grow < M);
            const float* gp = A + (size_t)(ok ? grow : 0) * KDIM + k0 + kq;
            cp_async16(smem_u32(&As[row * 36 + kq]), gp, ok ? 16 : 0);
        }
        constexpr int BC = BN * 4 / 256;
        #pragma unroll
        for (int i = 0; i < BC; i++) {
            int c = tid + i * 256;
            int nrow = c >> 2;
            int hq = (c & 3) * 8;
            const __half* gp = Bt + (size_t)(bn + nrow) * KDIM + k0 + hq;
            cp_async16(smem_u32(&Bs[nrow * 40 + hq]), gp, 16);
        }
        cp_commit();
    };

    load_stage(0, 0);

    for (int t = 0; t < ktiles; t++) {
        if (t + 1 < ktiles) load_stage((t + 1) & 1, (t + 1) * 32);
        else cp_commit();
        cp_wait<1>();
        __syncthreads();

        const float* As = Asm + (t & 1) * A_STAGE;
        const __half* Bs = Bsm + (t & 1) * B_STAGE;
        const unsigned bbase = smem_u32(Bs) + (unsigned)(brow0 * 40 + bkoff) * 2;

        #pragma unroll
        for (int kk = 0; kk < 32; kk += 16) {
            unsigned a[2][4];
            #pragma unroll
            for (int mt = 0; mt < 2; mt++) {
                int rb = warp_m * 32 + mt * 16 + g;
                float2 p0 = *(const float2*)&As[rb * 36 + kk + 2 * tg];
                float2 p1 = *(const float2*)&As[(rb + 8) * 36 + kk + 2 * tg];
                float2 p2 = *(const float2*)&As[rb * 36 + kk + 8 + 2 * tg];
                float2 p3 = *(const float2*)&As[(rb + 8) * 36 + kk + 8 + 2 * tg];
                a[mt][0] = pack_h2(p0.x, p0.y);
                a[mt][1] = pack_h2(p1.x, p1.y);
                a[mt][2] = pack_h2(p2.x, p2.y);
                a[mt][3] = pack_h2(p3.x, p3.y);
            }
            #pragma unroll
            for (int np = 0; np < NP; np++) {
                unsigned b0, b1, b2, b3;
                ldsm_x4(b0, b1, b2, b3, bbase + np * 16 * 40 * 2 + kk * 2);
                #pragma unroll
                for (int mt = 0; mt < 2; mt++) {
                    mma_f16(acc[mt][2 * np][0], acc[mt][2 * np][1], acc[mt][2 * np][2], acc[mt][2 * np][3],
                            a[mt][0], a[mt][1], a[mt][2], a[mt][3], b0, b1);
                    mma_f16(acc[mt][2 * np + 1][0], acc[mt][2 * np + 1][1], acc[mt][2 * np + 1][2], acc[mt][2 * np + 1][3],
                            a[mt][0], a[mt][1], a[mt][2], a[mt][3], b2, b3);
                }
            }
        }
        __syncthreads();
    }

    #pragma unroll
    for (int mt = 0; mt < 2; mt++) {
        #pragma unroll
        for (int nt = 0; nt < NT; nt++) {
            int col = bn + warp_n * (BN / 2) + nt * 8 + tg * 2;
            int r0 = bm + warp_m * 32 + mt * 16 + g;
            int r1 = r0 + 8;
            if (r0 < M)
                *(__half2*)&C[(size_t)r0 * N + col] = __floats2half2_rn(acc[mt][nt][0], acc[mt][nt][1]);
            if (r1 < M)
                *(__half2*)&C[(size_t)r1 * N + col] = __floats2half2_rn(acc[mt][nt][2], acc[mt][nt][3]);
        }
    }
}

// ---------------------------------------------------------------------------
// GEMM2: A fp16 (h), B = W2^T fp16 [n][k]. BM=128, BN=64, BK=32.
// ---------------------------------------------------------------------------
__global__ __launch_bounds__(256) void gemm2_kernel(
    const __half* __restrict__ A, const __half* __restrict__ Bt,
    __half* __restrict__ C, int M, int N, int K) {
    constexpr int BN = 64, NT = BN / 16, NP = NT / 2;  // 4, 2
    constexpr int A_STAGE = 128 * 56;    // halves
    constexpr int B_STAGE = BN * 40;     // halves
    extern __shared__ char smraw[];
    __half* Asm = (__half*)smraw;
    __half* Bsm = (__half*)(smraw + 2 * A_STAGE * 2);

    const int tid = threadIdx.x;
    const int lane = tid & 31;
    const int wid = tid >> 5;
    const int warp_m = wid & 3;
    const int warp_n = wid >> 2;
    const int bm = blockIdx.y * 128;
    const int bn = blockIdx.x * BN;
    const int g = lane >> 2;
    const int tg = lane & 3;
    const int lr = lane & 7;
    const int sel = lane >> 3;
    const int arow0 = warp_m * 32 + (sel & 1) * 8 + lr;
    const int akoff = ((sel >> 1) & 1) * 8;
    const int brow0 = warp_n * (BN / 2) + ((sel >> 1) & 1) * 8 + lr;
    const int bkoff = (sel & 1) * 8;

    float acc[2][NT][4];
    #pragma unroll
    for (int i = 0; i < 2; i++)
        #pragma unroll
        for (int j = 0; j < NT; j++)
            #pragma unroll
            for (int c = 0; c < 4; c++) acc[i][j][c] = 0.0f;

    const int ktiles = K / 32;

    auto load_stage = [&](int s, int k0) {
        __half* As = Asm + s * A_STAGE;
        __half* Bs = Bsm + s * B_STAGE;
        #pragma unroll
        for (int i = 0; i < 2; i++) {
            int c = tid + i * 256;
            int row = c >> 2;
            int hq = (c & 3) * 8;
            int grow = bm + row;
            int ok = (grow < M);
            const __half* gp = A + (size_t)(ok ? grow : 0) * K + k0 + hq;
            cp_async16(smem_u32(&As[row * 56 + hq]), gp, ok ? 16 : 0);
        }
        {
            int c = tid;
            int nrow = c >> 2;
            int hq = (c & 3) * 8;
            const __half* gp = Bt + (size_t)(bn + nrow) * K + k0 + hq;
            cp_async16(smem_u32(&Bs[nrow * 40 + hq]), gp, 16);
        }
        cp_commit();
    };

    load_stage(0, 0);

    for (int t = 0; t < ktiles; t++) {
        if (t + 1 < ktiles) load_stage((t + 1) & 1, (t + 1) * 32);
        else cp_commit();
        cp_wait<1>();
        __syncthreads();

        const __half* As = Asm + (t & 1) * A_STAGE;
        const __half* Bs = Bsm + (t & 1) * B_STAGE;
        const unsigned abase = smem_u32(As) + (unsigned)(arow0 * 56 + akoff) * 2;
        const unsigned bbase = smem_u32(Bs) + (unsigned)(brow0 * 40 + bkoff) * 2;

        #pragma unroll
        for (int kk = 0; kk < 32; kk += 16) {
            unsigned a[2][4];
            #pragma unroll
            for (int mt = 0; mt < 2; mt++)
                ldsm_x4(a[mt][0], a[mt][1], a[mt][2], a[mt][3],
                        abase + mt * 16 * 56 * 2 + kk * 2);
            #pragma unroll
            for (int np = 0; np < NP; np++) {
                unsigned b0, b1, b2, b3;
                ldsm_x4(b0, b1, b2, b3, bbase + np * 16 * 40 * 2 + kk * 2);
                #pragma unroll
                for (int mt = 0; mt < 2; mt++) {
                    mma_f16(acc[mt][2 * np][0], acc[mt][2 * np][1], acc[mt][2 * np][2], acc[mt][2 * np][3],
                            a[mt][0], a[mt][1], a[mt][2], a[mt][3], b0, b1);
                    mma_f16(acc[mt][2 * np + 1][0], acc[mt][2 * np + 1][1], acc[mt][2 * np + 1][2], acc[mt][2 * np + 1][3],
                            a[mt][0], a[mt][1], a[mt][2], a[mt][3], b2, b3);
                }
            }
        }
        __syncthreads();
    }

    #pragma unroll
    for (int mt = 0; mt < 2; mt++) {
        #pragma unroll
        for (int nt = 0; nt < NT; nt++) {
            int col = bn + warp_n * (BN / 2) + nt * 8 + tg * 2;
            int r0 = bm + warp_m * 32 + mt * 16 + g;
            int r1 = r0 + 8;
            if (r0 < M)
                *(__half2*)&C[(size_t)r0 * N + col] = __floats2half2_rn(acc[mt][nt][0], acc[mt][nt][1]);
            if (r1 < M)
                *(__half2*)&C[(size_t)r1 * N + col] = __floats2half2_rn(acc[mt][nt][2], acc[mt][nt][3]);
        }
    }
}

// ---------------------------------------------------------------------------
// Gather layer 1 (F=256): warp/node, 8 feats/lane, 4-edge unroll. ELL rows.
// (Round-13 exact version: fp32 FFMA + cvt; f32x2 packing regressed in R14.)
// ---------------------------------------------------------------------------
__global__ void gather1_kernel(const int* __restrict__ cnt, const int2* __restrict__ csr,
                               const __half* __restrict__ sup, const float* __restrict__ b,
                               __half* __restrict__ h, int n) {
    int node = blockIdx.x * 8 + (threadIdx.x >> 5);
    if (node >= n) return;
    int lane = threadIdx.x & 31;
    int p0 = node * ELL_PAD;
    int deg = cnt[node];
    if (deg > ELL_PAD) deg = ELL_PAD;
    int p1 = p0 + deg;
    float acc[8] = {};
    int p = p0;
    for (; p + 4 <= p1; p += 4) {
        int2 e0 = __ldg(&csr[p]);
        int2 e1 = __ldg(&csr[p + 1]);
        int2 e2 = __ldg(&csr[p + 2]);
        int2 e3 = __ldg(&csr[p + 3]);
        float w0 = __low2float(*(__half2*)&e0.y);
        float w1 = __low2float(*(__half2*)&e1.y);
        float w2 = __low2float(*(__half2*)&e2.y);
        float w3 = __low2float(*(__half2*)&e3.y);
        uint4 r0 = *(const uint4*)&sup[(size_t)e0.x * FAN_MID + lane * 8];
        uint4 r1 = *(const uint4*)&sup[(size_t)e1.x * FAN_MID + lane * 8];
        uint4 r2 = *(const uint4*)&sup[(size_t)e2.x * FAN_MID + lane * 8];
        uint4 r3 = *(const uint4*)&sup[(size_t)e3.x * FAN_MID + lane * 8];
        float2 f;
        f = __half22float2(*(__half2*)&r0.x); acc[0] += w0 * f.x; acc[1] += w0 * f.y;
        f = __half22float2(*(__half2*)&r0.y); acc[2] += w0 * f.x; acc[3] += w0 * f.y;
        f = __half22float2(*(__half2*)&r0.z); acc[4] += w0 * f.x; acc[5] += w0 * f.y;
        f = __half22float2(*(__half2*)&r0.w); acc[6] += w0 * f.x; acc[7] += w0 * f.y;
        f = __half22float2(*(__half2*)&r1.x); acc[0] += w1 * f.x; acc[1] += w1 * f.y;
        f = __half22float2(*(__half2*)&r1.y); acc[2] += w1 * f.x; acc[3] += w1 * f.y;
        f = __half22float2(*(__half2*)&r1.z); acc[4] += w1 * f.x; acc[5] += w1 * f.y;
        f = __half22float2(*(__half2*)&r1.w); acc[6] += w1 * f.x; acc[7] += w1 * f.y;
        f = __half22float2(*(__half2*)&r2.x); acc[0] += w2 * f.x; acc[1] += w2 * f.y;
        f = __half22float2(*(__half2*)&r2.y); acc[2] += w2 * f.x; acc[3] += w2 * f.y;
        f = __half22float2(*(__half2*)&r2.z); acc[4] += w2 * f.x; acc[5] += w2 * f.y;
        f = __half22float2(*(__half2*)&r2.w); acc[6] += w2 * f.x; acc[7] += w2 * f.y;
        f = __half22float2(*(__half2*)&r3.x); acc[0] += w3 * f.x; acc[1] += w3 * f.y;
        f = __half22float2(*(__half2*)&r3.y); acc[2] += w3 * f.x; acc[3] += w3 * f.y;
        f = __half22float2(*(__half2*)&r3.z); acc[4] += w3 * f.x; acc[5] += w3 * f.y;
        f = __half22float2(*(__half2*)&r3.w); acc[6] += w3 * f.x; acc[7] += w3 * f.y;
    }
    for (; p < p1; p++) {
        int2 e0 = __ldg(&csr[p]);
        float w0 = __low2float(*(__half2*)&e0.y);
        uint4 r0 = *(const uint4*)&sup[(size_t)e0.x * FAN_MID + lane * 8];
        float2 f;
        f = __half22float2(*(__half2*)&r0.x); acc[0] += w0 * f.x; acc[1] += w0 * f.y;
        f = __half22float2(*(__half2*)&r0.y); acc[2] += w0 * f.x; acc[3] += w0 * f.y;
        f = __half22float2(*(__half2*)&r0.z); acc[4] += w0 * f.x; acc[5] += w0 * f.y;
        f = __half22float2(*(__half2*)&r0.w); acc[6] += w0 * f.x; acc[7] += w0 * f.y;
    }
    float4 b0 = *(const float4*)&b[lane * 8];
    float4 b1 = *(const float4*)&b[lane * 8 + 4];
    acc[0] += b0.x; acc[1] += b0.y; acc[2] += b0.z; acc[3] += b0.w;
    acc[4] += b1.x; acc[5] += b1.y; acc[6] += b1.z; acc[7] += b1.w;
    #pragma unroll
    for (int j = 0; j < 8; j++) acc[j] = (acc[j] > 0.f) ? acc[j] : 0.01f * acc[j];
    uint4 outw;
    *(__half2*)&outw.x = __floats2half2_rn(acc[0], acc[1]);
    *(__half2*)&outw.y = __floats2half2_rn(acc[2], acc[3]);
    *(__half2*)&outw.z = __floats2half2_rn(acc[4], acc[5]);
    *(__half2*)&outw.w = __floats2half2_rn(acc[6], acc[7]);
    *(uint4*)&h[(size_t)node * FAN_MID + lane * 8] = outw;
}

// ---------------------------------------------------------------------------
// Gather layer 2 (F=64) fused with bias + log_softmax. 4-edge unroll. ELL rows.
// ---------------------------------------------------------------------------
__global__ void gather2_lsm_kernel(const int* __restrict__ cnt, const int2* __restrict__ csr,
                                   const __half* __restrict__ sup, const float* __restrict__ b,
                                   float* __restrict__ out, int n) {
    int node = blockIdx.x * 8 + (threadIdx.x >> 5);
    if (node >= n) return;
    int lane = threadIdx.x & 31;
    int p0 = node * ELL_PAD;
    int deg = cnt[node];
    if (deg > ELL_PAD) deg = ELL_PAD;
    int p1 = p0 + deg;
    float a0 = 0.f, a1 = 0.f;
    int p = p0;
    for (; p + 4 <= p1; p += 4) {
        int2 e0 = __ldg(&csr[p]);
        int2 e1 = __ldg(&csr[p + 1]);
        int2 e2 = __ldg(&csr[p + 2]);
        int2 e3 = __ldg(&csr[p + 3]);
        float w0 = __high2float(*(__half2*)&e0.y);
        float w1 = __high2float(*(__half2*)&e1.y);
        float w2 = __high2float(*(__half2*)&e2.y);
        float w3 = __high2float(*(__half2*)&e3.y);
        float2 f0 = __half22float2(*(const __half2*)&sup[(size_t)e0.x * FAN_OUT + lane * 2]);
        float2 f1 = __half22float2(*(const __half2*)&sup[(size_t)e1.x * FAN_OUT + lane * 2]);
        float2 f2 = __half22float2(*(const __half2*)&sup[(size_t)e2.x * FAN_OUT + lane * 2]);
        float2 f3 = __half22float2(*(const __half2*)&sup[(size_t)e3.x * FAN_OUT + lane * 2]);
        a0 += w0 * f0.x + w1 * f1.x + w2 * f2.x + w3 * f3.x;
        a1 += w0 * f0.y + w1 * f1.y + w2 * f2.y + w3 * f3.y;
    }
    for (; p < p1; p++) {
        int2 e0 = __ldg(&csr[p]);
        float w0 = __high2float(*(__half2*)&e0.y);
        float2 f0 = __half22float2(*(const __half2*)&sup[(size_t)e0.x * FAN_OUT + lane * 2]);
        a0 += w0 * f0.x;
        a1 += w0 * f0.y;
    }
    a0 += b[lane * 2];
    a1 += b[lane * 2 + 1];
    float m = fmaxf(a0, a1);
    #pragma unroll
    for (int o = 16; o; o >>= 1) m = fmaxf(m, __shfl_xor_sync(0xFFFFFFFFu, m, o));
    float s2 = expf(a0 - m) + expf(a1 - m);
    #pragma unroll
    for (int o = 16; o; o >>= 1) s2 += __shfl_xor_sync(0xFFFFFFFFu, s2, o);
    float lse = m + logf(s2);
    out[(size_t)node * FAN_OUT + lane * 2]     = a0 - lse;
    out[(size_t)node * FAN_OUT + lane * 2 + 1] = a1 - lse;
}

// ---------------------------------------------------------------------------
// Launch: prep -> fork {fill || GEMM1} -> join -> gather1 -> GEMM2 -> gather2
// fill is L2-atomic latency-bound (issue 2.4%); GEMM1 is tensor-bound and now
// reads x only once -- unlike round 4's failed overlap, L2 pressure is low.
// ---------------------------------------------------------------------------
extern "C" void kernel_launch(void* const* d_in, const int* in_sizes, int n_in,
                              void* d_out, int out_size) {
    const float* x        = (const float*)d_in[0];
    const int*   edge_src = (const int*)  d_in[1];
    const int*   edge_dst = (const int*)  d_in[2];
    const float* edge_w1  = (const float*)d_in[3];
    const float* edge_w2  = (const float*)d_in[4];
    const float* W1       = (const float*)d_in[5];
    const float* b1       = (const float*)d_in[6];
    const float* W2       = (const float*)d_in[7];
    const float* b2       = (const float*)d_in[8];
    float* out = (float*)d_out;

    const int E = in_sizes[1];
    const int N = in_sizes[0] / FAN_IN;

    __half *sup1, *h, *sup2, *w1t, *w2t;
    int *cnt;
    int2 *csr;
    cudaGetSymbolAddress((void**)&sup1, g_sup1);
    cudaGetSymbolAddress((void**)&h, g_h);
    cudaGetSymbolAddress((void**)&sup2, g_sup2);
    cudaGetSymbolAddress((void**)&w1t, g_w1t);
    cudaGetSymbolAddress((void**)&w2t, g_w2t);
    cudaGetSymbolAddress((void**)&cnt, g_cnt);
    cudaGetSymbolAddress((void**)&csr, g_csr);

    constexpr int SMEM_G1 = 2 * 128 * 36 * 4 + 2 * 256 * 40 * 2;   // 77824
    constexpr int SMEM_G2 = 2 * 128 * 56 * 2 + 2 * 64 * 40 * 2;    // 38912
    static cudaStream_t s_side = nullptr;
    static cudaEvent_t ev_fork = nullptr, ev_join = nullptr;
    if (s_side == nullptr) {
        cudaFuncSetAttribute(gemm1_kernel<256, FAN_IN>,
                             cudaFuncAttributeMaxDynamicSharedMemorySize, SMEM_G1);
        cudaFuncSetAttribute(gemm2_kernel,
                             cudaFuncAttributeMaxDynamicSharedMemorySize, SMEM_G2);
        cudaStreamCreateWithFlags(&s_side, cudaStreamNonBlocking);
        cudaEventCreateWithFlags(&ev_fork, cudaEventDisableTiming);
        cudaEventCreateWithFlags(&ev_join, cudaEventDisableTiming);
    }

    // --- Prep: weight transpose-convert + zero cnt (one kernel) ---
    prep_kernel<<<512, 256>>>(W1, W2, w1t, w2t, cnt);

    // --- Fork: fill (side) || GEMM1 (main) ---
    cudaEventRecord(ev_fork, 0);
    cudaStreamWaitEvent(s_side, ev_fork, 0);

    fill_kernel<<<1024, 256, 0, s_side>>>(edge_src, edge_dst, edge_w1, edge_w2, cnt, csr, E);
    cudaEventRecord(ev_join, s_side);

    {
        dim3 grid(1, (N + 127) / 128);
        gemm1_kernel<256, FAN_IN><<<grid, 256, SMEM_G1>>>(x, w1t, sup1, N, FAN_MID);
    }

    // --- Join ---
    cudaStreamWaitEvent(0, ev_join, 0);

    // h = lrelu(A @ sup1 + b1), fp16
    gather1_kernel<<<(N + 7) / 8, 256>>>(cnt, csr, sup1, b1, h, N);

    // --- Layer 2: sup2 = h @ W2 ---
    {
        dim3 grid(FAN_OUT / 64, (N + 127) / 128);
        gemm2_kernel<<<grid, 256, SMEM_G2>>>(h, w2t, sup2, N, FAN_OUT, FAN_MID);
    }
    // out = log_softmax(A @ sup2 + b2)
    gather2_lsm_kernel<<<(N + 7) / 8, 256>>>(cnt, csr, sup2, b2, out, N);
}